// round 12
// baseline (speedup 1.0000x reference)
#include <cuda_runtime.h>

#define DEVINL __device__ __forceinline__

namespace {

constexpr int NOFF = 44;
constexpr int H    = 16;
constexpr int NPOS = 8192;
constexpr int HD   = 64;
constexpr int POS_PER_CTA = 256;
constexpr int NTHREADS    = 512;
constexpr float SC = 0.125f;
constexpr int MAX_OFF = 1536;
constexpr unsigned FULL = 0xffffffffu;

__host__ __device__ constexpr int off_at(int i) {
    return i <= 32 ? i
         : i == 33 ? 48   : i == 34 ? 64   : i == 35 ? 96
         : i == 36 ? 128  : i == 37 ? 192  : i == 38 ? 256
         : i == 39 ? 384  : i == 40 ? 512  : i == 41 ? 768
         : i == 42 ? 1024 : 1536;
}

struct Smem {
    float  se[NOFF * HD];
    float  bias[NOFF];
    float2 cs[NOFF];
    int    doff[NOFF];
};

DEVINL float grp_sum(float x) {
    x += __shfl_xor_sync(FULL, x, 1);
    x += __shfl_xor_sync(FULL, x, 2);
    x += __shfl_xor_sync(FULL, x, 4);
    return x;
}
DEVINL float grp_max(float x) {
    x = fmaxf(x, __shfl_xor_sync(FULL, x, 1));
    x = fmaxf(x, __shfl_xor_sync(FULL, x, 2));
    x = fmaxf(x, __shfl_xor_sync(FULL, x, 4));
    return x;
}

DEVINL float4 f4zero() { return make_float4(0.f, 0.f, 0.f, 0.f); }

DEVINL void pf_l1(const float* p) {
    asm volatile("prefetch.global.L1 [%0];" :: "l"(p));
}

DEVINL void load_row2(bool stream, const float* __restrict__ row, int c,
                      float4& a, float4& b) {
    const float4* pa = reinterpret_cast<const float4*>(row + 4 * c);
    const float4* pb = reinterpret_cast<const float4*>(row + 32 + 4 * c);
    if (stream) { a = __ldcs(pa); b = __ldcs(pb); }
    else        { a = __ldg(pa);  b = __ldg(pb);  }
}

DEVINL float d8(const float4& qa, const float4& qb,
                const float4& ra, const float4& rb) {
    float t = qa.x * ra.x;
    t = fmaf(qa.y, ra.y, t);
    t = fmaf(qa.z, ra.z, t);
    t = fmaf(qa.w, ra.w, t);
    t = fmaf(qb.x, rb.x, t);
    t = fmaf(qb.y, rb.y, t);
    t = fmaf(qb.z, rb.z, t);
    t = fmaf(qb.w, rb.w, t);
    return t;
}
DEVINL float d8s(const float4& qa, const float4& qb,
                 const float4& ra, const float4& rb,
                 const float4& sa, const float4& sb) {
    float t = qa.x * (ra.x + sa.x);
    t = fmaf(qa.y, ra.y + sa.y, t);
    t = fmaf(qa.z, ra.z + sa.z, t);
    t = fmaf(qa.w, ra.w + sa.w, t);
    t = fmaf(qb.x, rb.x + sb.x, t);
    t = fmaf(qb.y, rb.y + sb.y, t);
    t = fmaf(qb.z, rb.z + sb.z, t);
    t = fmaf(qb.w, rb.w + sb.w, t);
    return t;
}

// 8 simultaneous 8-lane reductions in 7 shfl.
DEVINL float treduce8(const float (&v)[8], int c) {
    const bool h4 = (c & 4) != 0;
    float k0 = (h4 ? v[4] : v[0]) + __shfl_xor_sync(FULL, h4 ? v[0] : v[4], 4);
    float k1 = (h4 ? v[5] : v[1]) + __shfl_xor_sync(FULL, h4 ? v[1] : v[5], 4);
    float k2 = (h4 ? v[6] : v[2]) + __shfl_xor_sync(FULL, h4 ? v[2] : v[6], 4);
    float k3 = (h4 ? v[7] : v[3]) + __shfl_xor_sync(FULL, h4 ? v[3] : v[7], 4);
    const bool h2 = (c & 2) != 0;
    float m0 = (h2 ? k2 : k0) + __shfl_xor_sync(FULL, h2 ? k0 : k2, 2);
    float m1 = (h2 ? k3 : k1) + __shfl_xor_sync(FULL, h2 ? k1 : k3, 2);
    const bool h1 = (c & 1) != 0;
    return (h1 ? m1 : m0) + __shfl_xor_sync(FULL, h1 ? m0 : m1, 1);
}

template <bool CHECK>
DEVINL void run_quad(int n, int c,
                     const float* __restrict__ qb,
                     const float* __restrict__ kb,
                     const float* __restrict__ vb,
                     float* __restrict__ ob,
                     const Smem& sm)
{
    const float* qr = qb + (size_t)n * HD;
    float4 qA[4], qB[4];
#pragma unroll
    for (int p = 0; p < 4; ++p) {
        qA[p] = __ldg(reinterpret_cast<const float4*>(qr + p * HD + 4 * c));
        qB[p] = __ldg(reinterpret_cast<const float4*>(qr + p * HD + 32 + 4 * c));
    }

    // ---- prefetch sparse k rows (consumed in batches 4-5, ~2000 cyc away) ----
#pragma unroll
    for (int i = 33; i < 44; ++i) {
        const int d = off_at(i);
#pragma unroll
        for (int p = 0; p < 4; ++p) {
            if (!CHECK || (n + p >= d)) {
                const float* row = kb + (size_t)(n + p - d) * HD;
                pf_l1(row + 4 * c);
                pf_l1(row + 32 + 4 * c);
            }
        }
    }

    float sl[4][6];

    // ---- dense batches b = 0..3 (offsets 8b..8b+7) ----
#pragma unroll
    for (int b = 0; b < 4; ++b) {
        float part[4][8];
#pragma unroll
        for (int jj = 0; jj < 8; ++jj) {
            const int i = 8 * b + jj;
            const float4 sa = *reinterpret_cast<const float4*>(&sm.se[i * HD + 4 * c]);
            const float4 sb = *reinterpret_cast<const float4*>(&sm.se[i * HD + 32 + 4 * c]);
#pragma unroll
            for (int p = 0; p < 4; ++p)
                part[p][jj] = d8(qA[p], qB[p], sa, sb);
        }
#pragma unroll
        for (int t = 0; t < 11; ++t) {
            const int dd = 8 * b - 3 + t;
            float4 ka, kc2;
            const bool rv = (dd <= 0) || !CHECK || (n >= dd);
            if (rv) load_row2(false, kb + (size_t)(n - dd) * HD, c, ka, kc2);
            else { ka = f4zero(); kc2 = f4zero(); }
#pragma unroll
            for (int p = 0; p < 4; ++p) {
                const int i = dd + p;
                if (i >= 8 * b && i < 8 * b + 8)
                    part[p][i - 8 * b] += d8(qA[p], qB[p], ka, kc2);
            }
        }
#pragma unroll
        for (int p = 0; p < 4; ++p) {
            const float hs = treduce8(part[p], c);
            const float bias = sm.bias[8 * b + c];
            bool valid = true;
            if (CHECK) valid = (n + p >= 8 * b + c);
            sl[p][b] = valid ? fmaf(hs, SC, bias) : -1e30f;
        }
    }

    // ---- batch 4: offsets 32..39 ----
    {
        float part[4][8];
#pragma unroll
        for (int jj = 0; jj < 8; ++jj) {
            const int i = 32 + jj;
            const int d = off_at(i);
            const float4 sa = *reinterpret_cast<const float4*>(&sm.se[i * HD + 4 * c]);
            const float4 sb = *reinterpret_cast<const float4*>(&sm.se[i * HD + 32 + 4 * c]);
#pragma unroll
            for (int p = 0; p < 4; ++p) {
                float4 ra, rb2;
                const bool v = !CHECK || (n + p >= d);
                if (v) load_row2(d >= 192, kb + (size_t)(n + p - d) * HD, c, ra, rb2);
                else { ra = f4zero(); rb2 = f4zero(); }
                part[p][jj] = d8s(qA[p], qB[p], ra, rb2, sa, sb);
            }
        }
#pragma unroll
        for (int p = 0; p < 4; ++p) {
            const float hs = treduce8(part[p], c);
            const float bias = sm.bias[32 + c];
            bool valid = true;
            if (CHECK) valid = (n + p >= sm.doff[32 + c]);
            sl[p][4] = valid ? fmaf(hs, SC, bias) : -1e30f;
        }
    }

    // ---- batch 5: offsets 40..43 ----
    {
        float part[4][8];
#pragma unroll
        for (int p = 0; p < 4; ++p) {
            part[p][4] = 0.f; part[p][5] = 0.f; part[p][6] = 0.f; part[p][7] = 0.f;
        }
#pragma unroll
        for (int jj = 0; jj < 4; ++jj) {
            const int i = 40 + jj;
            const int d = off_at(i);
            const float4 sa = *reinterpret_cast<const float4*>(&sm.se[i * HD + 4 * c]);
            const float4 sb = *reinterpret_cast<const float4*>(&sm.se[i * HD + 32 + 4 * c]);
#pragma unroll
            for (int p = 0; p < 4; ++p) {
                float4 ra, rb2;
                const bool v = !CHECK || (n + p >= d);
                if (v) load_row2(true, kb + (size_t)(n + p - d) * HD, c, ra, rb2);
                else { ra = f4zero(); rb2 = f4zero(); }
                part[p][jj] = d8s(qA[p], qB[p], ra, rb2, sa, sb);
            }
        }
#pragma unroll
        for (int p = 0; p < 4; ++p) {
            const float hs = treduce8(part[p], c);
            const float bias = sm.bias[40 + (c & 3)];
            bool valid = (c < 4);
            if (CHECK) valid = valid && (n + p >= sm.doff[40 + (c & 3)]);
            sl[p][5] = valid ? fmaf(hs, SC, bias) : -1e30f;
        }
    }

    // ---- prefetch sparse v rows (consumed right after softmax) ----
#pragma unroll
    for (int i = 33; i < 44; ++i) {
        const int d = off_at(i);
#pragma unroll
        for (int p = 0; p < 4; ++p) {
            if (!CHECK || (n + p >= d)) {
                const float* row = vb + (size_t)(n + p - d) * HD;
                pf_l1(row + 4 * c);
                pf_l1(row + 32 + 4 * c);
            }
        }
    }

    // ---- softmax (distributed, deferred normalization) ----
    float inv[4];
    float ee[4][6];
#pragma unroll
    for (int p = 0; p < 4; ++p) {
        float m = sl[p][0];
#pragma unroll
        for (int j = 1; j < 6; ++j) m = fmaxf(m, sl[p][j]);
        m = grp_max(m);
        float sum = 0.f;
#pragma unroll
        for (int j = 0; j < 6; ++j) {
            const float e = __expf(sl[p][j] - m);
            ee[p][j] = e;
            sum += e;
        }
        sum = grp_sum(sum);
        inv[p] = __fdividef(1.f, sum);
    }

    // ---- output phase (inv folded into weights) ----
    float4 oA[4], oB[4];
#pragma unroll
    for (int p = 0; p < 4; ++p) { oA[p] = f4zero(); oB[p] = f4zero(); }

    auto wgt = [&](int i, int p) -> float2 {
        const float e = __shfl_sync(FULL, ee[p][i >> 3], i & 7, 8);
        const float pw = e * inv[p];
        const float2 cs = sm.cs[i];
        return make_float2(pw * cs.x, pw * cs.y);
    };
    auto racc = [&](int p, float2 w, const float4& va, const float4& vb2) {
        oA[p].x = fmaf(w.x, va.x, oA[p].x);  oA[p].x = fmaf(-w.y, va.y, oA[p].x);
        oA[p].y = fmaf(w.y, va.x, oA[p].y);  oA[p].y = fmaf( w.x, va.y, oA[p].y);
        oA[p].z = fmaf(w.x, va.z, oA[p].z);  oA[p].z = fmaf(-w.y, va.w, oA[p].z);
        oA[p].w = fmaf(w.y, va.z, oA[p].w);  oA[p].w = fmaf( w.x, va.w, oA[p].w);
        oB[p].x = fmaf(w.x, vb2.x, oB[p].x); oB[p].x = fmaf(-w.y, vb2.y, oB[p].x);
        oB[p].y = fmaf(w.y, vb2.x, oB[p].y); oB[p].y = fmaf( w.x, vb2.y, oB[p].y);
        oB[p].z = fmaf(w.x, vb2.z, oB[p].z); oB[p].z = fmaf(-w.y, vb2.w, oB[p].z);
        oB[p].w = fmaf(w.y, vb2.z, oB[p].w); oB[p].w = fmaf( w.x, vb2.w, oB[p].w);
    };

#pragma unroll
    for (int t = 0; t < 36; ++t) {
        const int dd = t - 3;
        float4 va, vb2;
        const bool rv = (dd <= 0) || !CHECK || (n >= dd);
        if (rv) load_row2(false, vb + (size_t)(n - dd) * HD, c, va, vb2);
        else { va = f4zero(); vb2 = f4zero(); }
#pragma unroll
        for (int p = 0; p < 4; ++p) {
            const int i = dd + p;
            if (i >= 0 && i <= 32) {
                const float2 w = wgt(i, p);
                racc(p, w, va, vb2);
            }
        }
    }
#pragma unroll
    for (int i = 33; i < 44; ++i) {
        const int d = off_at(i);
#pragma unroll
        for (int p = 0; p < 4; ++p) {
            float4 va, vb2;
            const bool v = !CHECK || (n + p >= d);
            if (v) load_row2(d >= 192, vb + (size_t)(n + p - d) * HD, c, va, vb2);
            else { va = f4zero(); vb2 = f4zero(); }
            const float2 w = wgt(i, p);
            racc(p, w, va, vb2);
        }
    }

    float* orow = ob + (size_t)n * HD;
#pragma unroll
    for (int p = 0; p < 4; ++p) {
        *reinterpret_cast<float4*>(orow + p * HD + 4 * c)      = oA[p];
        *reinterpret_cast<float4*>(orow + p * HD + 32 + 4 * c) = oB[p];
    }
}

__global__ void __launch_bounds__(NTHREADS, 1)
dsqg_kernel(const float* __restrict__ q, const float* __restrict__ k,
            const float* __restrict__ v, const float* __restrict__ pos_bias,
            const float* __restrict__ se, const float* __restrict__ phase,
            float* __restrict__ out)
{
    __shared__ Smem sm;
    const int bh  = blockIdx.y;
    const int h   = bh & (H - 1);
    const int tid = threadIdx.x;

    for (int idx = tid; idx < NOFF * HD; idx += NTHREADS) sm.se[idx] = se[idx];
    if (tid < NOFF) {
        sm.bias[tid] = pos_bias[tid * H + h];
        sm.doff[tid] = off_at(tid);
        float ss, cc;
        sincosf(phase[tid * H + h], &ss, &cc);
        sm.cs[tid] = make_float2(cc, ss);
    }
    __syncthreads();

    const size_t base = (size_t)bh * NPOS * HD;
    const float* qbp = q + base;
    const float* kbp = k + base;
    const float* vbp = v + base;
    float*       obp = out + base;

    const int warp = tid >> 5;
    const int lane = tid & 31;
    const int g    = lane >> 3;
    const int c    = lane & 7;
    const int n0   = blockIdx.x * POS_PER_CTA;
    const int n    = n0 + (warp * 4 + g) * 4;

    if (n0 >= MAX_OFF) run_quad<false>(n, c, qbp, kbp, vbp, obp, sm);
    else               run_quad<true >(n, c, qbp, kbp, vbp, obp, sm);
}

} // namespace

extern "C" void kernel_launch(void* const* d_in, const int* in_sizes, int n_in,
                              void* d_out, int out_size)
{
    const float* q  = (const float*)d_in[0];
    const float* k  = (const float*)d_in[1];
    const float* v  = (const float*)d_in[2];
    const float* pb = (const float*)d_in[3];
    const float* se = (const float*)d_in[4];
    const float* ph = (const float*)d_in[5];
    float* out = (float*)d_out;

    const int B = in_sizes[0] / (H * NPOS * HD);   // expect 2
    dim3 grid(NPOS / POS_PER_CTA, B * H);
    dsqg_kernel<<<grid, NTHREADS>>>(q, k, v, pb, se, ph, out);
}

// round 13
// speedup vs baseline: 1.0508x; 1.0508x over previous
#include <cuda_runtime.h>

#define DEVINL __device__ __forceinline__

namespace {

constexpr int NOFF = 44;
constexpr int H    = 16;
constexpr int NPOS = 8192;
constexpr int HD   = 64;
constexpr int NTHREADS    = 256;   // 8 warps; 3 CTAs/SM -> 24 warps
constexpr int POS_PER_CTA = 64;    // 8 warps * 4 groups * 2 positions
constexpr float SC = 0.125f;
constexpr int MAX_OFF = 1536;
constexpr unsigned FULL = 0xffffffffu;

__host__ __device__ constexpr int off_at(int i) {
    return i <= 32 ? i
         : i == 33 ? 48   : i == 34 ? 64   : i == 35 ? 96
         : i == 36 ? 128  : i == 37 ? 192  : i == 38 ? 256
         : i == 39 ? 384  : i == 40 ? 512  : i == 41 ? 768
         : i == 42 ? 1024 : 1536;
}

struct Smem {
    float  se[NOFF * HD];
    float  bias[NOFF];
    float2 cs[NOFF];
    int    doff[NOFF];
};

DEVINL float grp_sum(float x) {
    x += __shfl_xor_sync(FULL, x, 1);
    x += __shfl_xor_sync(FULL, x, 2);
    x += __shfl_xor_sync(FULL, x, 4);
    return x;
}
DEVINL float grp_max(float x) {
    x = fmaxf(x, __shfl_xor_sync(FULL, x, 1));
    x = fmaxf(x, __shfl_xor_sync(FULL, x, 2));
    x = fmaxf(x, __shfl_xor_sync(FULL, x, 4));
    return x;
}

DEVINL float4 f4zero() { return make_float4(0.f, 0.f, 0.f, 0.f); }

DEVINL void load_row2(bool stream, const float* __restrict__ row, int c,
                      float4& a, float4& b) {
    const float4* pa = reinterpret_cast<const float4*>(row + 4 * c);
    const float4* pb = reinterpret_cast<const float4*>(row + 32 + 4 * c);
    if (stream) { a = __ldcs(pa); b = __ldcs(pb); }
    else        { a = __ldg(pa);  b = __ldg(pb);  }
}

DEVINL float d8(const float4& qa, const float4& qb,
                const float4& ra, const float4& rb) {
    float t = qa.x * ra.x;
    t = fmaf(qa.y, ra.y, t);
    t = fmaf(qa.z, ra.z, t);
    t = fmaf(qa.w, ra.w, t);
    t = fmaf(qb.x, rb.x, t);
    t = fmaf(qb.y, rb.y, t);
    t = fmaf(qb.z, rb.z, t);
    t = fmaf(qb.w, rb.w, t);
    return t;
}
DEVINL float d8s(const float4& qa, const float4& qb,
                 const float4& ra, const float4& rb,
                 const float4& sa, const float4& sb) {
    float t = qa.x * (ra.x + sa.x);
    t = fmaf(qa.y, ra.y + sa.y, t);
    t = fmaf(qa.z, ra.z + sa.z, t);
    t = fmaf(qa.w, ra.w + sa.w, t);
    t = fmaf(qb.x, rb.x + sb.x, t);
    t = fmaf(qb.y, rb.y + sb.y, t);
    t = fmaf(qb.z, rb.z + sb.z, t);
    t = fmaf(qb.w, rb.w + sb.w, t);
    return t;
}

// 8 simultaneous 8-lane reductions in 7 shfl.
DEVINL float treduce8(const float (&v)[8], int c) {
    const bool h4 = (c & 4) != 0;
    float k0 = (h4 ? v[4] : v[0]) + __shfl_xor_sync(FULL, h4 ? v[0] : v[4], 4);
    float k1 = (h4 ? v[5] : v[1]) + __shfl_xor_sync(FULL, h4 ? v[1] : v[5], 4);
    float k2 = (h4 ? v[6] : v[2]) + __shfl_xor_sync(FULL, h4 ? v[2] : v[6], 4);
    float k3 = (h4 ? v[7] : v[3]) + __shfl_xor_sync(FULL, h4 ? v[3] : v[7], 4);
    const bool h2 = (c & 2) != 0;
    float m0 = (h2 ? k2 : k0) + __shfl_xor_sync(FULL, h2 ? k0 : k2, 2);
    float m1 = (h2 ? k3 : k1) + __shfl_xor_sync(FULL, h2 ? k1 : k3, 2);
    const bool h1 = (c & 1) != 0;
    return (h1 ? m1 : m0) + __shfl_xor_sync(FULL, h1 ? m0 : m1, 1);
}

// One 8-lane group handles positions (n, n+1); lane c covers dims [4c,4c+4)
// and [32+4c,32+4c+4). Score (p,i) lives in lane i&7, slot i>>3.
template <bool CHECK>
DEVINL void run_pair(int n, int c,
                     const float* __restrict__ qb,
                     const float* __restrict__ kb,
                     const float* __restrict__ vb,
                     float* __restrict__ ob,
                     const Smem& sm)
{
    const float* qr = qb + (size_t)n * HD;
    float4 qA[2], qB[2];
#pragma unroll
    for (int p = 0; p < 2; ++p) {
        qA[p] = __ldg(reinterpret_cast<const float4*>(qr + p * HD + 4 * c));
        qB[p] = __ldg(reinterpret_cast<const float4*>(qr + p * HD + 32 + 4 * c));
    }

    float sl[2][6];

    // ---- dense batches b = 0..3 (offsets 8b..8b+7); rows 2-way shared ----
#pragma unroll
    for (int b = 0; b < 4; ++b) {
        float part[2][8];
#pragma unroll
        for (int jj = 0; jj < 8; ++jj) {
            const int i = 8 * b + jj;
            const float4 sa = *reinterpret_cast<const float4*>(&sm.se[i * HD + 4 * c]);
            const float4 sb = *reinterpret_cast<const float4*>(&sm.se[i * HD + 32 + 4 * c]);
#pragma unroll
            for (int p = 0; p < 2; ++p)
                part[p][jj] = d8(qA[p], qB[p], sa, sb);
        }
        // rows dd = 8b-1 .. 8b+7; row n-dd serves (p, i = dd+p)
#pragma unroll
        for (int t = 0; t < 9; ++t) {
            const int dd = 8 * b - 1 + t;
            float4 ka, kc2;
            const bool rv = (dd <= 0) || !CHECK || (n >= dd);
            if (rv) load_row2(false, kb + (size_t)(n - dd) * HD, c, ka, kc2);
            else { ka = f4zero(); kc2 = f4zero(); }
#pragma unroll
            for (int p = 0; p < 2; ++p) {
                const int i = dd + p;
                if (i >= 8 * b && i < 8 * b + 8)
                    part[p][i - 8 * b] += d8(qA[p], qB[p], ka, kc2);
            }
        }
#pragma unroll
        for (int p = 0; p < 2; ++p) {
            const float hs = treduce8(part[p], c);
            const float bias = sm.bias[8 * b + c];
            bool valid = true;
            if (CHECK) valid = (n + p >= 8 * b + c);
            sl[p][b] = valid ? fmaf(hs, SC, bias) : -1e30f;
        }
    }

    // ---- batch 4: offsets 32..39 (per-position rows) ----
    {
        float part[2][8];
#pragma unroll
        for (int jj = 0; jj < 8; ++jj) {
            const int i = 32 + jj;
            const int d = off_at(i);
            const float4 sa = *reinterpret_cast<const float4*>(&sm.se[i * HD + 4 * c]);
            const float4 sb = *reinterpret_cast<const float4*>(&sm.se[i * HD + 32 + 4 * c]);
#pragma unroll
            for (int p = 0; p < 2; ++p) {
                float4 ra, rb2;
                const bool v = !CHECK || (n + p >= d);
                if (v) load_row2(d >= 192, kb + (size_t)(n + p - d) * HD, c, ra, rb2);
                else { ra = f4zero(); rb2 = f4zero(); }
                part[p][jj] = d8s(qA[p], qB[p], ra, rb2, sa, sb);
            }
        }
#pragma unroll
        for (int p = 0; p < 2; ++p) {
            const float hs = treduce8(part[p], c);
            const float bias = sm.bias[32 + c];
            bool valid = true;
            if (CHECK) valid = (n + p >= sm.doff[32 + c]);
            sl[p][4] = valid ? fmaf(hs, SC, bias) : -1e30f;
        }
    }

    // ---- batch 5: offsets 40..43 ----
    {
        float part[2][8];
#pragma unroll
        for (int p = 0; p < 2; ++p) {
            part[p][4] = 0.f; part[p][5] = 0.f; part[p][6] = 0.f; part[p][7] = 0.f;
        }
#pragma unroll
        for (int jj = 0; jj < 4; ++jj) {
            const int i = 40 + jj;
            const int d = off_at(i);
            const float4 sa = *reinterpret_cast<const float4*>(&sm.se[i * HD + 4 * c]);
            const float4 sb = *reinterpret_cast<const float4*>(&sm.se[i * HD + 32 + 4 * c]);
#pragma unroll
            for (int p = 0; p < 2; ++p) {
                float4 ra, rb2;
                const bool v = !CHECK || (n + p >= d);
                if (v) load_row2(true, kb + (size_t)(n + p - d) * HD, c, ra, rb2);
                else { ra = f4zero(); rb2 = f4zero(); }
                part[p][jj] = d8s(qA[p], qB[p], ra, rb2, sa, sb);
            }
        }
#pragma unroll
        for (int p = 0; p < 2; ++p) {
            const float hs = treduce8(part[p], c);
            const float bias = sm.bias[40 + (c & 3)];
            bool valid = (c < 4);
            if (CHECK) valid = valid && (n + p >= sm.doff[40 + (c & 3)]);
            sl[p][5] = valid ? fmaf(hs, SC, bias) : -1e30f;
        }
    }

    // ---- softmax (distributed, deferred normalization) ----
    float inv[2];
    float ee[2][6];
#pragma unroll
    for (int p = 0; p < 2; ++p) {
        float m = sl[p][0];
#pragma unroll
        for (int j = 1; j < 6; ++j) m = fmaxf(m, sl[p][j]);
        m = grp_max(m);
        float sum = 0.f;
#pragma unroll
        for (int j = 0; j < 6; ++j) {
            const float e = __expf(sl[p][j] - m);
            ee[p][j] = e;
            sum += e;
        }
        sum = grp_sum(sum);
        inv[p] = __fdividef(1.f, sum);
    }

    // ---- output phase (inv folded into weights) ----
    float4 oA[2], oB[2];
#pragma unroll
    for (int p = 0; p < 2; ++p) { oA[p] = f4zero(); oB[p] = f4zero(); }

    auto wgt = [&](int i, int p) -> float2 {
        const float e = __shfl_sync(FULL, ee[p][i >> 3], i & 7, 8);
        const float pw = e * inv[p];
        const float2 cs = sm.cs[i];
        return make_float2(pw * cs.x, pw * cs.y);
    };
    auto racc = [&](int p, float2 w, const float4& va, const float4& vb2) {
        oA[p].x = fmaf(w.x, va.x, oA[p].x);  oA[p].x = fmaf(-w.y, va.y, oA[p].x);
        oA[p].y = fmaf(w.y, va.x, oA[p].y);  oA[p].y = fmaf( w.x, va.y, oA[p].y);
        oA[p].z = fmaf(w.x, va.z, oA[p].z);  oA[p].z = fmaf(-w.y, va.w, oA[p].z);
        oA[p].w = fmaf(w.y, va.z, oA[p].w);  oA[p].w = fmaf( w.x, va.w, oA[p].w);
        oB[p].x = fmaf(w.x, vb2.x, oB[p].x); oB[p].x = fmaf(-w.y, vb2.y, oB[p].x);
        oB[p].y = fmaf(w.y, vb2.x, oB[p].y); oB[p].y = fmaf( w.x, vb2.y, oB[p].y);
        oB[p].z = fmaf(w.x, vb2.z, oB[p].z); oB[p].z = fmaf(-w.y, vb2.w, oB[p].z);
        oB[p].w = fmaf(w.y, vb2.z, oB[p].w); oB[p].w = fmaf( w.x, vb2.w, oB[p].w);
    };

    // dense v rows dd = -1..32 (34 rows, 2-way shared)
#pragma unroll
    for (int t = 0; t < 34; ++t) {
        const int dd = t - 1;
        float4 va, vb2;
        const bool rv = (dd <= 0) || !CHECK || (n >= dd);
        if (rv) load_row2(false, vb + (size_t)(n - dd) * HD, c, va, vb2);
        else { va = f4zero(); vb2 = f4zero(); }
#pragma unroll
        for (int p = 0; p < 2; ++p) {
            const int i = dd + p;
            if (i >= 0 && i <= 32) {
                const float2 w = wgt(i, p);
                racc(p, w, va, vb2);
            }
        }
    }
    // sparse v rows per position
#pragma unroll
    for (int i = 33; i < 44; ++i) {
        const int d = off_at(i);
#pragma unroll
        for (int p = 0; p < 2; ++p) {
            float4 va, vb2;
            const bool v = !CHECK || (n + p >= d);
            if (v) load_row2(d >= 192, vb + (size_t)(n + p - d) * HD, c, va, vb2);
            else { va = f4zero(); vb2 = f4zero(); }
            const float2 w = wgt(i, p);
            racc(p, w, va, vb2);
        }
    }

    float* orow = ob + (size_t)n * HD;
#pragma unroll
    for (int p = 0; p < 2; ++p) {
        *reinterpret_cast<float4*>(orow + p * HD + 4 * c)      = oA[p];
        *reinterpret_cast<float4*>(orow + p * HD + 32 + 4 * c) = oB[p];
    }
}

__global__ void __launch_bounds__(NTHREADS, 3)
dsqg_kernel(const float* __restrict__ q, const float* __restrict__ k,
            const float* __restrict__ v, const float* __restrict__ pos_bias,
            const float* __restrict__ se, const float* __restrict__ phase,
            float* __restrict__ out)
{
    __shared__ Smem sm;
    const int bh  = blockIdx.y;
    const int h   = bh & (H - 1);
    const int tid = threadIdx.x;

    for (int idx = tid; idx < NOFF * HD; idx += NTHREADS) sm.se[idx] = se[idx];
    if (tid < NOFF) {
        sm.bias[tid] = pos_bias[tid * H + h];
        sm.doff[tid] = off_at(tid);
        float ss, cc;
        sincosf(phase[tid * H + h], &ss, &cc);
        sm.cs[tid] = make_float2(cc, ss);
    }
    __syncthreads();

    const size_t base = (size_t)bh * NPOS * HD;
    const float* qbp = q + base;
    const float* kbp = k + base;
    const float* vbp = v + base;
    float*       obp = out + base;

    const int warp = tid >> 5;    // 0..7
    const int lane = tid & 31;
    const int g    = lane >> 3;   // group in warp
    const int c    = lane & 7;    // dim chunk
    const int n0   = blockIdx.x * POS_PER_CTA;
    const int n    = n0 + (warp * 4 + g) * 2;

    if (n0 >= MAX_OFF) run_pair<false>(n, c, qbp, kbp, vbp, obp, sm);
    else               run_pair<true >(n, c, qbp, kbp, vbp, obp, sm);
}

} // namespace

extern "C" void kernel_launch(void* const* d_in, const int* in_sizes, int n_in,
                              void* d_out, int out_size)
{
    const float* q  = (const float*)d_in[0];
    const float* k  = (const float*)d_in[1];
    const float* v  = (const float*)d_in[2];
    const float* pb = (const float*)d_in[3];
    const float* se = (const float*)d_in[4];
    const float* ph = (const float*)d_in[5];
    float* out = (float*)d_out;

    const int B = in_sizes[0] / (H * NPOS * HD);   // expect 2
    dim3 grid(NPOS / POS_PER_CTA, B * H);
    dsqg_kernel<<<grid, NTHREADS>>>(q, k, v, pb, se, ph, out);
}